// round 15
// baseline (speedup 1.0000x reference)
#include <cuda_runtime.h>
#include <cuda_bf16.h>

#define BATCH 1024
#define SEQ   256
#define HALF  128

__device__ __forceinline__ float ex2f(float x) {
    float r; asm("ex2.approx.f32 %0, %1;" : "=f"(r) : "f"(x)); return r;
}
__device__ __forceinline__ float rcpf(float x) {
    float r; asm("rcp.approx.f32 %0, %1;" : "=f"(r) : "f"(x)); return r;
}

// Accurate fast tanh: tanh(x) = 1 - 2/(exp(2x)+1); ex2+rcp approx, ~1e-7 abs err.
__device__ __forceinline__ float fast_tanh(float x) {
    const float c = 2.88539008177792681472f;   // 2 * log2(e)
    float e = ex2f(x * c);
    float r = rcpf(e + 1.0f);
    return fmaf(-2.0f, r, 1.0f);
}

// R15: DISCRIMINATOR — R8 shape (1 CTA/batch, 128 thr, 2 rows/thread, K/V in
// SMEM, K pre-scaled by 0.5*log2e, one-pass softmax) but ALL-SCALAR FFMA.
// Rationale: R8..R14 показали fma% pinned ~54% and immunity to occupancy/ILP/
// instruction-count changes -> hypothesis: PTX f32x2 ops issue at rt=4 (no
// throughput gain over scalar) and the fma pipe is actually near-saturated.
// Scalar removes all pack/unpack ALU movs and gives ptxas full freedom.
__global__ __launch_bounds__(HALF) void hybrid_attn_kernel(
    const float* __restrict__ x,
    const float* __restrict__ Wq, const float* __restrict__ Wk, const float* __restrict__ Wv,
    const float* __restrict__ W1, const float* __restrict__ b1,
    const float* __restrict__ W2, const float* __restrict__ b2,
    const float* __restrict__ W3, const float* __restrict__ b3,
    float* __restrict__ out)
{
    __shared__ float4 sk[SEQ];   // (k0*cs, k1*cs, k2*cs, k3*cs)
    __shared__ float4 sv[SEQ];   // (v0, v1, v2, v3)
    __shared__ float sWq[16], sWk[16], sWv[16];
    __shared__ float sW1[32], sb1[8], sW2[32], sb2[4], sW3[4], sb3;

    const int tid = threadIdx.x;
    const int b   = blockIdx.x;

    if (tid < 16) { sWq[tid] = Wq[tid]; sWk[tid] = Wk[tid]; sWv[tid] = Wv[tid]; }
    if (tid < 32) { sW1[tid] = W1[tid]; sW2[tid] = W2[tid]; }
    if (tid < 8)  { sb1[tid] = b1[tid]; }
    if (tid < 4)  { sb2[tid] = b2[tid]; sW3[tid] = W3[tid]; }
    if (tid == 0) { sb3 = b3[0]; }

    const float4 xa = reinterpret_cast<const float4*>(x)[b * SEQ + tid];
    const float4 xb = reinterpret_cast<const float4*>(x)[b * SEQ + tid + HALF];

    __syncthreads();   // weights staged before any read

    #define PROJ(W, xv, o0, o1, o2, o3)                                        \
        o0 = xv.x*W[0] + xv.y*W[4] + xv.z*W[8]  + xv.w*W[12];                  \
        o1 = xv.x*W[1] + xv.y*W[5] + xv.z*W[9]  + xv.w*W[13];                  \
        o2 = xv.x*W[2] + xv.y*W[6] + xv.z*W[10] + xv.w*W[14];                  \
        o3 = xv.x*W[3] + xv.y*W[7] + xv.z*W[11] + xv.w*W[15];

    const float cs = 0.72134752044448170368f;   // 0.5 * log2(e), folded into K

    float qa0,qa1,qa2,qa3, qb0,qb1,qb2,qb3;
    float t0,t1,t2,t3;

    PROJ(sWq, xa, qa0,qa1,qa2,qa3)
    PROJ(sWq, xb, qb0,qb1,qb2,qb3)

    PROJ(sWk, xa, t0,t1,t2,t3)
    sk[tid]        = make_float4(t0*cs, t1*cs, t2*cs, t3*cs);
    PROJ(sWk, xb, t0,t1,t2,t3)
    sk[tid + HALF] = make_float4(t0*cs, t1*cs, t2*cs, t3*cs);

    PROJ(sWv, xa, t0,t1,t2,t3)
    sv[tid]        = make_float4(t0, t1, t2, t3);
    PROJ(sWv, xb, t0,t1,t2,t3)
    sv[tid + HALF] = make_float4(t0, t1, t2, t3);
    #undef PROJ

    __syncthreads();

    float aA0=0.f, aA1=0.f, aA2=0.f, aA3=0.f, lA=0.f;
    float aB0=0.f, aB1=0.f, aB2=0.f, aB3=0.f, lB=0.f;

    #pragma unroll 8
    for (int t = 0; t < SEQ; ++t) {
        const float4 kk = sk[t];   // one LDS.128, broadcast
        const float4 vv = sv[t];   // one LDS.128, broadcast

        float sA = fmaf(qa0, kk.x, fmaf(qa1, kk.y, fmaf(qa2, kk.z, qa3 * kk.w)));
        float sB = fmaf(qb0, kk.x, fmaf(qb1, kk.y, fmaf(qb2, kk.z, qb3 * kk.w)));
        const float eA = ex2f(sA);
        const float eB = ex2f(sB);

        aA0 = fmaf(eA, vv.x, aA0);
        aA1 = fmaf(eA, vv.y, aA1);
        aA2 = fmaf(eA, vv.z, aA2);
        aA3 = fmaf(eA, vv.w, aA3);
        lA += eA;

        aB0 = fmaf(eB, vv.x, aB0);
        aB1 = fmaf(eB, vv.y, aB1);
        aB2 = fmaf(eB, vv.z, aB2);
        aB3 = fmaf(eB, vv.w, aB3);
        lB += eB;
    }

    // MLP head per row: 4 -> 8 (tanh) -> 4 (tanh) -> 1
    #pragma unroll
    for (int r = 0; r < 2; ++r) {
        float a0, a1, a2, a3, l;
        if (r == 0) { a0=aA0; a1=aA1; a2=aA2; a3=aA3; l=lA; }
        else        { a0=aB0; a1=aB1; a2=aB2; a3=aB3; l=lB; }
        const float inv = 1.0f / l;
        a0 *= inv; a1 *= inv; a2 *= inv; a3 *= inv;

        float h1[8];
        #pragma unroll
        for (int i = 0; i < 8; ++i) {
            float u = a0*sW1[0*8+i] + a1*sW1[1*8+i] + a2*sW1[2*8+i] + a3*sW1[3*8+i] + sb1[i];
            h1[i] = fast_tanh(u);
        }
        float h2[4];
        #pragma unroll
        for (int i = 0; i < 4; ++i) {
            float u = sb2[i];
            #pragma unroll
            for (int j = 0; j < 8; ++j) u += h1[j] * sW2[j*4+i];
            h2[i] = fast_tanh(u);
        }
        float o = h2[0]*sW3[0] + h2[1]*sW3[1] + h2[2]*sW3[2] + h2[3]*sW3[3] + sb3;
        out[b * SEQ + tid + r * HALF] = o;
    }
}

extern "C" void kernel_launch(void* const* d_in, const int* in_sizes, int n_in,
                              void* d_out, int out_size) {
    const float* x  = (const float*)d_in[0];
    const float* Wq = (const float*)d_in[1];
    const float* Wk = (const float*)d_in[2];
    const float* Wv = (const float*)d_in[3];
    const float* W1 = (const float*)d_in[4];
    const float* b1 = (const float*)d_in[5];
    const float* W2 = (const float*)d_in[6];
    const float* b2 = (const float*)d_in[7];
    const float* W3 = (const float*)d_in[8];
    const float* b3 = (const float*)d_in[9];
    float* out = (float*)d_out;

    hybrid_attn_kernel<<<BATCH, HALF>>>(x, Wq, Wk, Wv, W1, b1, W2, b2, W3, b3, out);
}

// round 17
// speedup vs baseline: 1.5142x; 1.5142x over previous
#include <cuda_runtime.h>
#include <cuda_bf16.h>
#include <cstdint>

#define BATCH 1024
#define SEQ   256
#define HALF  128
#define NCHUNK 16          // KV chunks of 16 columns
#define CHUNK  16
#define SP_STRIDE 260      // score-tile row stride (floats); conflict-free

typedef unsigned long long u64;

__device__ __forceinline__ u64 pack2(float lo, float hi) {
    u64 r; asm("mov.b64 %0, {%1,%2};" : "=l"(r) : "f"(lo), "f"(hi)); return r;
}
__device__ __forceinline__ void unpack2(u64 v, float& lo, float& hi) {
    asm("mov.b64 {%0,%1}, %2;" : "=f"(lo), "=f"(hi) : "l"(v));
}
__device__ __forceinline__ u64 ffma2(u64 a, u64 b, u64 c) {
    u64 d; asm("fma.rn.f32x2 %0, %1, %2, %3;" : "=l"(d) : "l"(a), "l"(b), "l"(c)); return d;
}
__device__ __forceinline__ u64 fadd2(u64 a, u64 b) {
    u64 d; asm("add.rn.f32x2 %0, %1, %2;" : "=l"(d) : "l"(a), "l"(b)); return d;
}
__device__ __forceinline__ float ex2f(float x) {
    float r; asm("ex2.approx.f32 %0, %1;" : "=f"(r) : "f"(x)); return r;
}
__device__ __forceinline__ float rcpf(float x) {
    float r; asm("rcp.approx.f32 %0, %1;" : "=f"(r) : "f"(x)); return r;
}
__device__ __forceinline__ float fast_tanh(float x) {
    const float c = 2.88539008177792681472f;   // 2*log2(e)
    float e = ex2f(x * c);
    float r = rcpf(e + 1.0f);
    return fmaf(-2.0f, r, 1.0f);
}

// split-tf32: hi = x with low 13 mantissa bits cleared; lo = x - hi (exact).
__device__ __forceinline__ void tf32_split(float x, uint32_t& hi, uint32_t& lo) {
    uint32_t xb = __float_as_uint(x);
    hi = xb & 0xFFFFE000u;
    float lof = x - __uint_as_float(hi);
    lo = __float_as_uint(lof) & 0xFFFFE000u;
}

__device__ __forceinline__ void mma_tf32(float& d0, float& d1, float& d2, float& d3,
                                         uint32_t a0, uint32_t a1, uint32_t b0) {
    uint32_t z = 0;
    asm volatile(
        "mma.sync.aligned.m16n8k8.row.col.f32.tf32.tf32.f32 "
        "{%0,%1,%2,%3}, {%4,%5,%6,%7}, {%8,%9}, {%0,%1,%2,%3};"
        : "+f"(d0), "+f"(d1), "+f"(d2), "+f"(d3)
        : "r"(a0), "r"(a1), "r"(z), "r"(z), "r"(b0), "r"(z));
}

// Hybrid: tensor-core GEMM1 (scores, split-tf32, K=4 padded to 8) into SMEM,
// scalar packed-f32x2 softmax+V-accumulate (GEMM2). Removes the 4-MAC dot
// (and its horizontal add) from the fp32 pipe, which R15 proved is the binder
// (~33us MAC floor at 9 MAC/row/t; now 5 MAC/row/t).
__global__ __launch_bounds__(HALF, 7) void hybrid_attn_kernel(
    const float* __restrict__ x,
    const float* __restrict__ Wq, const float* __restrict__ Wk, const float* __restrict__ Wv,
    const float* __restrict__ W1, const float* __restrict__ b1,
    const float* __restrict__ W2, const float* __restrict__ b2,
    const float* __restrict__ W3, const float* __restrict__ b3,
    float* __restrict__ out)
{
    __shared__ float sQ[SEQ * 4];          // q rows, pre-scaled by 0.5*log2(e)
    __shared__ float sK[SEQ * 4];          // k rows (raw)
    __shared__ ulonglong2 sv[SEQ];         // packed V: .x=(v0,v1) .y=(v2,v3)
    __shared__ float sSp[CHUNK * SP_STRIDE];  // score tile [col][row]
    __shared__ float sWq[16], sWk[16], sWv[16];
    __shared__ float sW1[32], sb1[8], sW2[32], sb2[4], sW3[4], sb3;

    const int tid = threadIdx.x;
    const int b   = blockIdx.x;
    const int lane = tid & 31;
    const int warp = tid >> 5;
    const int g    = lane >> 2;   // groupID
    const int t4   = lane & 3;    // threadID_in_group

    if (tid < 16) { sWq[tid] = Wq[tid]; sWk[tid] = Wk[tid]; sWv[tid] = Wv[tid]; }
    if (tid < 32) { sW1[tid] = W1[tid]; sW2[tid] = W2[tid]; }
    if (tid < 8)  { sb1[tid] = b1[tid]; }
    if (tid < 4)  { sb2[tid] = b2[tid]; sW3[tid] = W3[tid]; }
    if (tid == 0) { sb3 = b3[0]; }

    const float4 xa = reinterpret_cast<const float4*>(x)[b * SEQ + tid];
    const float4 xb = reinterpret_cast<const float4*>(x)[b * SEQ + tid + HALF];

    __syncthreads();   // weights staged

    #define PROJ(W, xv, o0, o1, o2, o3)                                        \
        o0 = xv.x*W[0] + xv.y*W[4] + xv.z*W[8]  + xv.w*W[12];                  \
        o1 = xv.x*W[1] + xv.y*W[5] + xv.z*W[9]  + xv.w*W[13];                  \
        o2 = xv.x*W[2] + xv.y*W[6] + xv.z*W[10] + xv.w*W[14];                  \
        o3 = xv.x*W[3] + xv.y*W[7] + xv.z*W[11] + xv.w*W[15];

    const float cs = 0.72134752044448170368f;   // 0.5 * log2(e) -> folded into Q

    {
        float t0,t1,t2,t3;
        float4* sQ4 = reinterpret_cast<float4*>(sQ);
        float4* sK4 = reinterpret_cast<float4*>(sK);

        PROJ(sWq, xa, t0,t1,t2,t3)
        sQ4[tid]        = make_float4(t0*cs, t1*cs, t2*cs, t3*cs);
        PROJ(sWq, xb, t0,t1,t2,t3)
        sQ4[tid + HALF] = make_float4(t0*cs, t1*cs, t2*cs, t3*cs);

        PROJ(sWk, xa, t0,t1,t2,t3)
        sK4[tid]        = make_float4(t0, t1, t2, t3);
        PROJ(sWk, xb, t0,t1,t2,t3)
        sK4[tid + HALF] = make_float4(t0, t1, t2, t3);

        PROJ(sWv, xa, t0,t1,t2,t3)
        sv[tid]        = make_ulonglong2(pack2(t0, t1), pack2(t2, t3));
        PROJ(sWv, xb, t0,t1,t2,t3)
        sv[tid + HALF] = make_ulonglong2(pack2(t0, t1), pack2(t2, t3));
    }
    #undef PROJ

    __syncthreads();

    u64 accA01 = 0, accA23 = 0, accB01 = 0, accB23 = 0;
    u64 lAB = 0;                                  // (sum eA, sum eB)

    for (int ch = 0; ch < NCHUNK; ++ch) {
        // ---- MMA phase: scores for 16 KV columns, all 256 rows ----
        // B fragments (k8n8, col-major): b0 = K[key = base + g][e = t4]; b1 = 0 (K=4).
        uint32_t b0h[2], b0l[2];
        #pragma unroll
        for (int nt = 0; nt < 2; ++nt) {
            float kv = sK[(ch*CHUNK + nt*8)*4 + lane];   // (base+g)*4 + t4 == base*4+lane
            tf32_split(kv, b0h[nt], b0l[nt]);
        }

        #pragma unroll
        for (int mt = 0; mt < 4; ++mt) {
            const int rowA = warp*64 + mt*16 + g;        // rows rowA and rowA+8
            float a0f = sQ[rowA*4 + t4];
            float a1f = sQ[(rowA+8)*4 + t4];
            uint32_t a0h,a0l,a1h,a1l;
            tf32_split(a0f, a0h, a0l);
            tf32_split(a1f, a1h, a1l);

            #pragma unroll
            for (int nt = 0; nt < 2; ++nt) {
                float d0=0.f, d1=0.f, d2=0.f, d3=0.f;
                mma_tf32(d0,d1,d2,d3, a0h,a1h, b0h[nt]);   // hi*hi
                mma_tf32(d0,d1,d2,d3, a0h,a1h, b0l[nt]);   // hi*lo
                mma_tf32(d0,d1,d2,d3, a0l,a1l, b0h[nt]);   // lo*hi
                // D frag: c0(r,2t4) c1(r,2t4+1) c2(r+8,2t4) c3(r+8,2t4+1)
                const int col = nt*8 + 2*t4;
                sSp[ col   *SP_STRIDE + rowA    ] = d0;
                sSp[(col+1)*SP_STRIDE + rowA    ] = d1;
                sSp[ col   *SP_STRIDE + rowA + 8] = d2;
                sSp[(col+1)*SP_STRIDE + rowA + 8] = d3;
            }
        }
        __syncthreads();

        // ---- scalar phase: exp + V accumulate for these 16 columns ----
        #pragma unroll
        for (int tt = 0; tt < CHUNK; ++tt) {
            const float sA = sSp[tt*SP_STRIDE + tid];
            const float sB = sSp[tt*SP_STRIDE + tid + HALF];
            const ulonglong2 vv = sv[ch*CHUNK + tt];

            const float eA = ex2f(sA);
            const float eB = ex2f(sB);

            const u64 eeA = pack2(eA, eA);
            accA01 = ffma2(eeA, vv.x, accA01);
            accA23 = ffma2(eeA, vv.y, accA23);

            const u64 eeB = pack2(eB, eB);
            accB01 = ffma2(eeB, vv.x, accB01);
            accB23 = ffma2(eeB, vv.y, accB23);

            lAB = fadd2(lAB, pack2(eA, eB));
        }
        __syncthreads();
    }

    float lA, lB;
    unpack2(lAB, lA, lB);

    // MLP head per row: 4 -> 8 (tanh) -> 4 (tanh) -> 1
    #pragma unroll
    for (int r = 0; r < 2; ++r) {
        float a0, a1, a2, a3, l;
        if (r == 0) { unpack2(accA01, a0, a1); unpack2(accA23, a2, a3); l = lA; }
        else        { unpack2(accB01, a0, a1); unpack2(accB23, a2, a3); l = lB; }
        const float inv = 1.0f / l;
        a0 *= inv; a1 *= inv; a2 *= inv; a3 *= inv;

        float h1[8];
        #pragma unroll
        for (int i = 0; i < 8; ++i) {
            float u = a0*sW1[0*8+i] + a1*sW1[1*8+i] + a2*sW1[2*8+i] + a3*sW1[3*8+i] + sb1[i];
            h1[i] = fast_tanh(u);
        }
        float h2[4];
        #pragma unroll
        for (int i = 0; i < 4; ++i) {
            float u = sb2[i];
            #pragma unroll
            for (int j = 0; j < 8; ++j) u += h1[j] * sW2[j*4+i];
            h2[i] = fast_tanh(u);
        }
        float o = h2[0]*sW3[0] + h2[1]*sW3[1] + h2[2]*sW3[2] + h2[3]*sW3[3] + sb3;
        out[b * SEQ + tid + r * HALF] = o;
    }
}

extern "C" void kernel_launch(void* const* d_in, const int* in_sizes, int n_in,
                              void* d_out, int out_size) {
    const float* x  = (const float*)d_in[0];
    const float* Wq = (const float*)d_in[1];
    const float* Wk = (const float*)d_in[2];
    const float* Wv = (const float*)d_in[3];
    const float* W1 = (const float*)d_in[4];
    const float* b1 = (const float*)d_in[5];
    const float* W2 = (const float*)d_in[6];
    const float* b2 = (const float*)d_in[7];
    const float* W3 = (const float*)d_in[8];
    const float* b3 = (const float*)d_in[9];
    float* out = (float*)d_out;

    hybrid_attn_kernel<<<BATCH, HALF>>>(x, Wq, Wk, Wv, W1, b1, W2, b2, W3, b3, out);
}